// round 12
// baseline (speedup 1.0000x reference)
#include <cuda_runtime.h>
#include <cuda_bf16.h>
#include <cstdint>

#define M_TOTAL 8192
#define N_TOTAL 4096
#define K_TOTAL 4096

// Quantized operands held as bf16 (int values in [-128,127] are EXACT in bf16)
__device__ __nv_bfloat16 g_xq[(size_t)M_TOTAL * K_TOTAL];   // 67 MB
__device__ __nv_bfloat16 g_wq[(size_t)N_TOTAL * K_TOTAL];   // 33.5 MB

// ---------------------------------------------------------------------------
// Fused quantize: first NX4 float4s are x -> trunc(clip(x/s)), rest are w cast.
// ---------------------------------------------------------------------------
#define NX4 ((M_TOTAL * K_TOTAL) / 4)
#define NW4 ((N_TOTAL * K_TOTAL) / 4)

__global__ void quant_fused_kernel(const float* __restrict__ x,
                                   const float* __restrict__ w,
                                   const float* __restrict__ iscale) {
    int i = blockIdx.x * blockDim.x + threadIdx.x;
    if (i < NX4) {
        float s = *iscale;
        float4 v = reinterpret_cast<const float4*>(x)[i];
        float q0 = truncf(fminf(fmaxf(__fdiv_rn(v.x, s), -128.f), 127.f));
        float q1 = truncf(fminf(fmaxf(__fdiv_rn(v.y, s), -128.f), 127.f));
        float q2 = truncf(fminf(fmaxf(__fdiv_rn(v.z, s), -128.f), 127.f));
        float q3 = truncf(fminf(fmaxf(__fdiv_rn(v.w, s), -128.f), 127.f));
        __nv_bfloat162 p0 = __floats2bfloat162_rn(q0, q1);
        __nv_bfloat162 p1 = __floats2bfloat162_rn(q2, q3);
        uint2 p = make_uint2(*(uint32_t*)&p0, *(uint32_t*)&p1);
        reinterpret_cast<uint2*>(g_xq)[i] = p;
    } else {
        int j = i - NX4;
        if (j >= NW4) return;
        float4 v = reinterpret_cast<const float4*>(w)[j];
        __nv_bfloat162 p0 = __floats2bfloat162_rn(v.x, v.y);
        __nv_bfloat162 p1 = __floats2bfloat162_rn(v.z, v.w);
        uint2 p = make_uint2(*(uint32_t*)&p0, *(uint32_t*)&p1);
        reinterpret_cast<uint2*>(g_wq)[j] = p;
    }
}

// ---------------------------------------------------------------------------
// bf16 GEMM via mma.sync.m16n8k16.f32.bf16.bf16.f32.
// Block tile 128x128 x BK=64 elems (128B rows, SW128), 3-stage cp.async with
// ONE barrier per k-iteration, ldmatrix.x4 fragments, warp tile 64x32.
// ---------------------------------------------------------------------------
#define BM 128
#define BN 128
#define BKE 64                      // K elements per chunk
#define BKB 128                     // K bytes per row (bf16)
#define KT (K_TOTAL / BKE)          // 64
#define A_TILE (BM * BKB)           // 16384 B
#define B_TILE (BN * BKB)           // 16384 B
#define STAGE_BYTES (A_TILE + B_TILE)          // 32768
#define SMEM_TOTAL (3 * STAGE_BYTES)           // 98304

static __device__ __forceinline__ uint32_t smem_u32(const void* p) {
    uint32_t a;
    asm("{ .reg .u64 t; cvta.to.shared.u64 t, %1; cvt.u32.u64 %0, t; }"
        : "=r"(a) : "l"(p));
    return a;
}
static __device__ __forceinline__ uint32_t sw128(uint32_t o) {
    return o ^ ((o >> 3) & 0x70);
}
static __device__ __forceinline__ void cp16(uint32_t saddr, const void* g) {
    asm volatile("cp.async.cg.shared.global [%0], [%1], 16;\n" :: "r"(saddr), "l"(g));
}
static __device__ __forceinline__ void ldsm4(uint32_t& r0, uint32_t& r1,
                                             uint32_t& r2, uint32_t& r3,
                                             uint32_t addr) {
    asm volatile("ldmatrix.sync.aligned.m8n8.x4.shared.b16 {%0,%1,%2,%3}, [%4];"
                 : "=r"(r0), "=r"(r1), "=r"(r2), "=r"(r3) : "r"(addr));
}

// cp.async a 128x64 A tile + 128x64 B tile (bf16) into SW128 smem stage
static __device__ __forceinline__ void load_stage(uint32_t s_u, int chunk,
                                                  int bm, int bn, int tid) {
    const int k0 = chunk * BKE;
    const uint32_t sb_u = s_u + A_TILE;
#pragma unroll
    for (int i = 0; i < 4; ++i) {               // A: 1024 x 16B
        int e = i * 256 + tid;
        int row = e >> 3, c16 = (e & 7) * 16;   // byte col within 128B row
        cp16(s_u + sw128(row * BKB + c16),
             g_xq + (size_t)(bm + row) * K_TOTAL + k0 + c16 / 2);
    }
#pragma unroll
    for (int i = 0; i < 4; ++i) {               // B: 1024 x 16B
        int e = i * 256 + tid;
        int row = e >> 3, c16 = (e & 7) * 16;
        cp16(sb_u + sw128(row * BKB + c16),
             g_wq + (size_t)(bn + row) * K_TOTAL + k0 + c16 / 2);
    }
}

__global__ __launch_bounds__(256, 2) void gemm_bf16_kernel(
    const float* __restrict__ wscale, const float* __restrict__ iscale,
    const float* __restrict__ bias, float* __restrict__ out) {
    extern __shared__ char smem[];
    const uint32_t smem_base = smem_u32(smem);

    const int tid = threadIdx.x;
    const int lane = tid & 31;
    const int warp = tid >> 5;
    const int warp_m = warp & 1;    // 2 warps along M (64 rows each)
    const int warp_n = warp >> 1;   // 4 warps along N (32 cols each)
    const int bm = blockIdx.y * BM;
    const int bn = blockIdx.x * BN;

    // ldmatrix lane mapping
    const int grp = lane >> 3, r8 = lane & 7;
    const int lrow = (grp & 1) * 8 + r8;
    const int lcol = (grp >> 1) * 16;           // byte offset within 32B k-slice

    float acc[4][4][4];
#pragma unroll
    for (int mi = 0; mi < 4; ++mi)
#pragma unroll
        for (int ni = 0; ni < 4; ++ni)
#pragma unroll
            for (int r = 0; r < 4; ++r) acc[mi][ni][r] = 0.f;

    // Prologue: chunks 0 and 1 into stages 0 and 1
    load_stage(smem_base, 0, bm, bn, tid);
    asm volatile("cp.async.commit_group;\n");
    load_stage(smem_base + STAGE_BYTES, 1, bm, bn, tid);
    asm volatile("cp.async.commit_group;\n");

    uint32_t stage_u = smem_base;               // compute stage for kt
    uint32_t pf_u = smem_base + 2 * STAGE_BYTES;  // prefetch target at kt

    for (int kt = 0; kt < KT; ++kt) {
        // chunk kt's copies (this thread's) complete; newest group may pend
        asm volatile("cp.async.wait_group 1;\n");
        // publish chunk kt to all warps AND prove all warps done with chunk kt-1
        __syncthreads();
        // prefetch chunk kt+2 into the stage chunk kt-1 just vacated
        if (kt + 2 < KT) load_stage(pf_u, kt + 2, bm, bn, tid);
        asm volatile("cp.async.commit_group;\n");

        const uint32_t sA = stage_u;
        const uint32_t sB = stage_u + A_TILE;
#pragma unroll
        for (int kk = 0; kk < 4; ++kk) {        // 4 x k16 slices (32B each)
            const int kcol = kk * 32 + lcol;
            uint32_t a[4][4];
#pragma unroll
            for (int mi = 0; mi < 4; ++mi) {
                uint32_t addr = sA + sw128(
                    (uint32_t)(warp_m * 64 + mi * 16 + lrow) * BKB + kcol);
                ldsm4(a[mi][0], a[mi][1], a[mi][2], a[mi][3], addr);
            }
            uint32_t b[4][2];
#pragma unroll
            for (int np = 0; np < 2; ++np) {
                uint32_t addr = sB + sw128(
                    (uint32_t)(warp_n * 32 + np * 16 + lrow) * BKB + kcol);
                uint32_t m0, m1, m2, m3;
                ldsm4(m0, m1, m2, m3, addr);
                b[2 * np][0] = m0; b[2 * np + 1][0] = m1;
                b[2 * np][1] = m2; b[2 * np + 1][1] = m3;
            }
#pragma unroll
            for (int mi = 0; mi < 4; ++mi)
#pragma unroll
                for (int ni = 0; ni < 4; ++ni) {
                    asm volatile(
                        "mma.sync.aligned.m16n8k16.row.col.f32.bf16.bf16.f32 "
                        "{%0,%1,%2,%3}, {%4,%5,%6,%7}, {%8,%9}, {%0,%1,%2,%3};\n"
                        : "+f"(acc[mi][ni][0]), "+f"(acc[mi][ni][1]),
                          "+f"(acc[mi][ni][2]), "+f"(acc[mi][ni][3])
                        : "r"(a[mi][0]), "r"(a[mi][1]), "r"(a[mi][2]), "r"(a[mi][3]),
                          "r"(b[ni][0]), "r"(b[ni][1]));
                }
        }
        // rotate ring: compute stage advances; vacated stage becomes prefetch
        uint32_t t = stage_u;
        stage_u = (stage_u == smem_base + 2 * STAGE_BYTES) ? smem_base
                                                           : stage_u + STAGE_BYTES;
        pf_u = t;
    }

    // Epilogue: dequant + bias (acc holds exact integer values in fp32)
    const float is = *iscale;
    const int gr = lane >> 2, gc = lane & 3;
#pragma unroll
    for (int mi = 0; mi < 4; ++mi) {
#pragma unroll
        for (int ni = 0; ni < 4; ++ni) {
            const int row = bm + warp_m * 64 + mi * 16 + gr;
            const int col = bn + warp_n * 32 + ni * 8 + gc * 2;
            const float s0 = wscale[col] * is;
            const float s1 = wscale[col + 1] * is;
            const float b0 = bias[col];
            const float b1 = bias[col + 1];
            float2 r0 = make_float2(fmaf(acc[mi][ni][0], s0, b0),
                                    fmaf(acc[mi][ni][1], s1, b1));
            float2 r1 = make_float2(fmaf(acc[mi][ni][2], s0, b0),
                                    fmaf(acc[mi][ni][3], s1, b1));
            *(float2*)(out + (size_t)row * N_TOTAL + col) = r0;
            *(float2*)(out + (size_t)(row + 8) * N_TOTAL + col) = r1;
        }
    }
}

// ---------------------------------------------------------------------------
// Inputs (metadata order): x, quant_weight, weight_scale, input_scale, bias
// ---------------------------------------------------------------------------
extern "C" void kernel_launch(void* const* d_in, const int* in_sizes, int n_in,
                              void* d_out, int out_size) {
    const float* x      = (const float*)d_in[0];
    const float* qw     = (const float*)d_in[1];
    const float* wscale = (const float*)d_in[2];
    const float* iscale = (const float*)d_in[3];
    const float* bias   = (const float*)d_in[4];
    float* out = (float*)d_out;

    cudaFuncSetAttribute(gemm_bf16_kernel,
                         cudaFuncAttributeMaxDynamicSharedMemorySize, SMEM_TOTAL);

    {   // fused quantize x + cast w -> bf16 ints
        int total = NX4 + NW4;
        quant_fused_kernel<<<(total + 255) / 256, 256>>>(x, qw, iscale);
    }
    {
        dim3 grid(N_TOTAL / BN, M_TOTAL / BM);  // (32, 64) = 2048 CTAs
        gemm_bf16_kernel<<<grid, 256, SMEM_TOTAL>>>(wscale, iscale, bias, out);
    }
}

// round 15
// speedup vs baseline: 1.5168x; 1.5168x over previous
#include <cuda_runtime.h>
#include <cuda_bf16.h>
#include <cstdint>

#define M_TOTAL 8192
#define N_TOTAL 4096
#define K_TOTAL 4096

// Quantized operands held as bf16 (int values in [-128,127] are EXACT in bf16)
__device__ __nv_bfloat16 g_xq[(size_t)M_TOTAL * K_TOTAL];   // 67 MB
__device__ __nv_bfloat16 g_wq[(size_t)N_TOTAL * K_TOTAL];   // 33.5 MB

// ---------------------------------------------------------------------------
// Fused quantize: first NX4 float4s are x -> trunc(clip(x/s)), rest are w cast.
// ---------------------------------------------------------------------------
#define NX4 ((M_TOTAL * K_TOTAL) / 4)
#define NW4 ((N_TOTAL * K_TOTAL) / 4)

__global__ void quant_fused_kernel(const float* __restrict__ x,
                                   const float* __restrict__ w,
                                   const float* __restrict__ iscale) {
    int i = blockIdx.x * blockDim.x + threadIdx.x;
    if (i < NX4) {
        float s = *iscale;
        float4 v = reinterpret_cast<const float4*>(x)[i];
        float q0 = truncf(fminf(fmaxf(__fdiv_rn(v.x, s), -128.f), 127.f));
        float q1 = truncf(fminf(fmaxf(__fdiv_rn(v.y, s), -128.f), 127.f));
        float q2 = truncf(fminf(fmaxf(__fdiv_rn(v.z, s), -128.f), 127.f));
        float q3 = truncf(fminf(fmaxf(__fdiv_rn(v.w, s), -128.f), 127.f));
        __nv_bfloat162 p0 = __floats2bfloat162_rn(q0, q1);
        __nv_bfloat162 p1 = __floats2bfloat162_rn(q2, q3);
        uint2 p = make_uint2(*(uint32_t*)&p0, *(uint32_t*)&p1);
        reinterpret_cast<uint2*>(g_xq)[i] = p;
    } else {
        int j = i - NX4;
        if (j >= NW4) return;
        float4 v = reinterpret_cast<const float4*>(w)[j];
        __nv_bfloat162 p0 = __floats2bfloat162_rn(v.x, v.y);
        __nv_bfloat162 p1 = __floats2bfloat162_rn(v.z, v.w);
        uint2 p = make_uint2(*(uint32_t*)&p0, *(uint32_t*)&p1);
        reinterpret_cast<uint2*>(g_wq)[j] = p;
    }
}

// ---------------------------------------------------------------------------
// bf16 GEMM via mma.sync.m16n8k16.f32.bf16.bf16.f32.  (R7 proven schedule)
// Block tile 128x128 x BK=64 elems (=128B rows, SW128), 3-stage cp.async,
// ldmatrix.x4 fragments, warp tile 64x32, fp32 accumulators.
// ---------------------------------------------------------------------------
#define BM 128
#define BN 128
#define BKE 64                      // K elements per chunk
#define BKB 128                     // K bytes per row (bf16)
#define KT (K_TOTAL / BKE)          // 64
#define A_TILE (BM * BKB)           // 16384 B
#define B_TILE (BN * BKB)           // 16384 B
#define STAGE_BYTES (A_TILE + B_TILE)          // 32768
#define SMEM_TOTAL (3 * STAGE_BYTES)           // 98304

static __device__ __forceinline__ uint32_t smem_u32(const void* p) {
    uint32_t a;
    asm("{ .reg .u64 t; cvta.to.shared.u64 t, %1; cvt.u32.u64 %0, t; }"
        : "=r"(a) : "l"(p));
    return a;
}
static __device__ __forceinline__ uint32_t sw128(uint32_t o) {
    return o ^ ((o >> 3) & 0x70);
}
static __device__ __forceinline__ void cp16(uint32_t saddr, const void* g) {
    asm volatile("cp.async.cg.shared.global [%0], [%1], 16;\n" :: "r"(saddr), "l"(g));
}
static __device__ __forceinline__ void ldsm4(uint32_t& r0, uint32_t& r1,
                                             uint32_t& r2, uint32_t& r3,
                                             uint32_t addr) {
    asm volatile("ldmatrix.sync.aligned.m8n8.x4.shared.b16 {%0,%1,%2,%3}, [%4];"
                 : "=r"(r0), "=r"(r1), "=r"(r2), "=r"(r3) : "r"(addr));
}

// cp.async a 128x64 A tile + 128x64 B tile (bf16) into SW128 smem stage
static __device__ __forceinline__ void load_stage(uint32_t s_u, int chunk,
                                                  int bm, int bn, int tid) {
    const int k0 = chunk * BKE;
    const uint32_t sb_u = s_u + A_TILE;
#pragma unroll
    for (int i = 0; i < 4; ++i) {               // A: 1024 x 16B
        int e = i * 256 + tid;
        int row = e >> 3, c16 = (e & 7) * 16;   // byte col within 128B row
        cp16(s_u + sw128(row * BKB + c16),
             g_xq + (size_t)(bm + row) * K_TOTAL + k0 + c16 / 2);
    }
#pragma unroll
    for (int i = 0; i < 4; ++i) {               // B: 1024 x 16B
        int e = i * 256 + tid;
        int row = e >> 3, c16 = (e & 7) * 16;
        cp16(sb_u + sw128(row * BKB + c16),
             g_wq + (size_t)(bn + row) * K_TOTAL + k0 + c16 / 2);
    }
}

__global__ __launch_bounds__(256, 2) void gemm_bf16_kernel(
    const float* __restrict__ wscale, const float* __restrict__ iscale,
    const float* __restrict__ bias, float* __restrict__ out) {
    extern __shared__ char smem[];
    const uint32_t smem_base = smem_u32(smem);

    const int tid = threadIdx.x;
    const int lane = tid & 31;
    const int warp = tid >> 5;
    const int warp_m = warp & 1;    // 2 warps along M (64 rows each)
    const int warp_n = warp >> 1;   // 4 warps along N (32 cols each)
    const int bm = blockIdx.y * BM;
    const int bn = blockIdx.x * BN;

    // ldmatrix lane mapping
    const int grp = lane >> 3, r8 = lane & 7;
    const int lrow = (grp & 1) * 8 + r8;
    const int lcol = (grp >> 1) * 16;           // byte offset within 32B k-slice

    float acc[4][4][4];
#pragma unroll
    for (int mi = 0; mi < 4; ++mi)
#pragma unroll
        for (int ni = 0; ni < 4; ++ni)
#pragma unroll
            for (int r = 0; r < 4; ++r) acc[mi][ni][r] = 0.f;

    // Prologue: chunks 0 and 1
    load_stage(smem_base, 0, bm, bn, tid);
    asm volatile("cp.async.commit_group;\n");
    load_stage(smem_base + STAGE_BYTES, 1, bm, bn, tid);
    asm volatile("cp.async.commit_group;\n");

    uint32_t stage_u = smem_base;
    uint32_t pf_u = smem_base + 2 * STAGE_BYTES;

    for (int kt = 0; kt < KT; ++kt) {
        if (kt + 2 < KT) load_stage(pf_u, kt + 2, bm, bn, tid);
        asm volatile("cp.async.commit_group;\n");
        asm volatile("cp.async.wait_group 2;\n");
        __syncthreads();

        const uint32_t sA = stage_u;
        const uint32_t sB = stage_u + A_TILE;
#pragma unroll
        for (int kk = 0; kk < 4; ++kk) {        // 4 x k16 slices (32B each)
            const int kcol = kk * 32 + lcol;
            uint32_t a[4][4];
#pragma unroll
            for (int mi = 0; mi < 4; ++mi) {
                uint32_t addr = sA + sw128(
                    (uint32_t)(warp_m * 64 + mi * 16 + lrow) * BKB + kcol);
                ldsm4(a[mi][0], a[mi][1], a[mi][2], a[mi][3], addr);
            }
            uint32_t b[4][2];
#pragma unroll
            for (int np = 0; np < 2; ++np) {    // 16 n-rows per LDSM
                uint32_t addr = sB + sw128(
                    (uint32_t)(warp_n * 32 + np * 16 + lrow) * BKB + kcol);
                uint32_t m0, m1, m2, m3;
                ldsm4(m0, m1, m2, m3, addr);
                b[2 * np][0] = m0; b[2 * np + 1][0] = m1;
                b[2 * np][1] = m2; b[2 * np + 1][1] = m3;
            }
#pragma unroll
            for (int mi = 0; mi < 4; ++mi)
#pragma unroll
                for (int ni = 0; ni < 4; ++ni) {
                    asm volatile(
                        "mma.sync.aligned.m16n8k16.row.col.f32.bf16.bf16.f32 "
                        "{%0,%1,%2,%3}, {%4,%5,%6,%7}, {%8,%9}, {%0,%1,%2,%3};\n"
                        : "+f"(acc[mi][ni][0]), "+f"(acc[mi][ni][1]),
                          "+f"(acc[mi][ni][2]), "+f"(acc[mi][ni][3])
                        : "r"(a[mi][0]), "r"(a[mi][1]), "r"(a[mi][2]), "r"(a[mi][3]),
                          "r"(b[ni][0]), "r"(b[ni][1]));
                }
        }
        __syncthreads();
        uint32_t t = stage_u;
        stage_u = (stage_u == smem_base + 2 * STAGE_BYTES) ? smem_base
                                                           : stage_u + STAGE_BYTES;
        pf_u = t;
    }

    // Epilogue: dequant + bias (acc holds exact integer values in fp32)
    const float is = *iscale;
    const int gr = lane >> 2, gc = lane & 3;
#pragma unroll
    for (int mi = 0; mi < 4; ++mi) {
#pragma unroll
        for (int ni = 0; ni < 4; ++ni) {
            const int row = bm + warp_m * 64 + mi * 16 + gr;
            const int col = bn + warp_n * 32 + ni * 8 + gc * 2;
            const float s0 = wscale[col] * is;
            const float s1 = wscale[col + 1] * is;
            const float b0 = bias[col];
            const float b1 = bias[col + 1];
            float2 r0 = make_float2(fmaf(acc[mi][ni][0], s0, b0),
                                    fmaf(acc[mi][ni][1], s1, b1));
            float2 r1 = make_float2(fmaf(acc[mi][ni][2], s0, b0),
                                    fmaf(acc[mi][ni][3], s1, b1));
            *(float2*)(out + (size_t)row * N_TOTAL + col) = r0;
            *(float2*)(out + (size_t)(row + 8) * N_TOTAL + col) = r1;
        }
    }
}

// ---------------------------------------------------------------------------
// Inputs (metadata order): x, quant_weight, weight_scale, input_scale, bias
// ---------------------------------------------------------------------------
extern "C" void kernel_launch(void* const* d_in, const int* in_sizes, int n_in,
                              void* d_out, int out_size) {
    const float* x      = (const float*)d_in[0];
    const float* qw     = (const float*)d_in[1];
    const float* wscale = (const float*)d_in[2];
    const float* iscale = (const float*)d_in[3];
    const float* bias   = (const float*)d_in[4];
    float* out = (float*)d_out;

    cudaFuncSetAttribute(gemm_bf16_kernel,
                         cudaFuncAttributeMaxDynamicSharedMemorySize, SMEM_TOTAL);

    {   // fused quantize x + cast w -> bf16 ints (one launch)
        int total = NX4 + NW4;
        quant_fused_kernel<<<(total + 255) / 256, 256>>>(x, qw, iscale);
    }
    {
        dim3 grid(N_TOTAL / BN, M_TOTAL / BM);  // (32, 64) = 2048 CTAs
        gemm_bf16_kernel<<<grid, 256, SMEM_TOTAL>>>(wscale, iscale, bias, out);
    }
}